// round 15
// baseline (speedup 1.0000x reference)
#include <cuda_runtime.h>

// ----------------------------------------------------------------------------
// 2-layer LSTM (B=256, T=1024, H=512, in=1) + final H->1 projection.
// ONE persistent kernel runs all 2*1024 timestep-GEMMs with a software grid
// barrier (128 co-resident blocks); cell state lives in registers; packed
// fp32x2 FMA inner loop with pre-duplicated A operand (zero pack MOVs).
// Graph = 2 nodes (persistent + projection): no multi-MB graph upload.
// ----------------------------------------------------------------------------

#define BB 256
#define TT 1024
#define HH 512
#define G4 2048              // 4*H
#define BH (BB*HH)           // 131072

#define TR 64                // batch rows per block
#define TC 16                // h-cols per block  (=> GC=64 G-cols, 4 gates)
#define GC 64
#define KB 16                // k-slice per staging iteration
#define ASTR 132             // padded stride of duplicated-A smem rows (2*TR+4)
#define NTHREADS 256
#define NBLK 128             // (256/TR) * (512/TC) = 4 * 32

// Persistent device state. g_zeroh is NEVER written -> stays zero across
// replays. g_h0 ping-pong and g_H2 are fully rewritten each replay.
__device__ float g_h0[2][BH];
__device__ float g_zeroh[BH];
__device__ float g_H2[(size_t)TT * BH];     // layer-1 hidden history [t][b][h]
__device__ unsigned g_count;                // barrier arrive counter (ends at 0)
__device__ unsigned g_gen;                  // barrier generation (monotonic)

// ---------------- packed f32x2 helpers --------------------------------------
__device__ __forceinline__ unsigned long long ffma2(unsigned long long a,
                                                    unsigned long long b,
                                                    unsigned long long c) {
    unsigned long long d;
    asm("fma.rn.f32x2 %0, %1, %2, %3;" : "=l"(d) : "l"(a), "l"(b), "l"(c));
    return d;
}
__device__ __forceinline__ void upk2(unsigned long long v, float& x, float& y) {
    asm("mov.b64 {%0, %1}, %2;" : "=f"(x), "=f"(y) : "l"(v));
}
__device__ __forceinline__ float sigmoidf_acc(float x) {
    return 0.5f * tanhf(0.5f * x) + 0.5f;   // accurate sigmoid via tanhf
}

// ---------------- software grid barrier (all NBLK blocks co-resident) -------
__device__ __forceinline__ void grid_bar(unsigned& gen) {
    __threadfence();
    __syncthreads();
    if (threadIdx.x == 0) {
        if (atomicAdd(&g_count, 1u) == NBLK - 1u) {
            g_count = 0u;
            __threadfence();
            atomicExch(&g_gen, gen + 1u);
        } else {
            while (*((volatile unsigned*)&g_gen) != gen + 1u) { }
        }
        __threadfence();
    }
    __syncthreads();
    gen += 1u;
}

// ---------------- one gate-GEMM: acc[4][2] = A @ W (tile 64x64 of G) --------
// A duplicated in smem as {a,a} pairs so both FFMA2 operands load as packed
// 64-bit values straight from shared memory (no register packing MOVs).
__device__ __forceinline__ void gemm_tile(
    const float* __restrict__ A1, const float* __restrict__ A2,
    const float* __restrict__ W1, const float* __restrict__ W2,
    int niter, int aoff, int boff,
    float* __restrict__ sA, float* __restrict__ sB,
    int tr4, int tc4, int a_row, int a_k, int b_kk, int b_q0,
    unsigned long long acc[4][2])
{
    #pragma unroll
    for (int i = 0; i < 4; ++i) { acc[i][0] = 0ULL; acc[i][1] = 0ULL; }

    float4 aR = *(const float4*)(A1 + aoff);         // iter 0 prefetch (k0=0)
    float4 bR = *(const float4*)(W1 + boff);

    for (int it = 0; it < niter; ++it) {
        __syncthreads();
        // stage: A duplicated pairs, B raw
        *(float2*)(&sA[(a_k + 0) * ASTR + 2 * a_row]) = make_float2(aR.x, aR.x);
        *(float2*)(&sA[(a_k + 1) * ASTR + 2 * a_row]) = make_float2(aR.y, aR.y);
        *(float2*)(&sA[(a_k + 2) * ASTR + 2 * a_row]) = make_float2(aR.z, aR.z);
        *(float2*)(&sA[(a_k + 3) * ASTR + 2 * a_row]) = make_float2(aR.w, aR.w);
        *(float4*)(&sB[b_kk * GC + b_q0]) = bR;
        __syncthreads();

        // prefetch next k-slice while computing this one
        if (it + 1 < niter) {
            const int nit = it + 1;
            const int seg = nit >> 5;                 // switches A1/W1 -> A2/W2
            const int k0  = (nit & 31) * KB;
            const float* A = seg ? A2 : A1;
            const float* W = seg ? W2 : W1;
            aR = *(const float4*)(A + aoff + k0);
            bR = *(const float4*)(W + boff + (size_t)k0 * G4);
        }

        // 16 k x (4 rows x 4 cols) : 3 LDS.128 + 8 FFMA2 per k
        #pragma unroll
        for (int kk = 0; kk < KB; ++kk) {
            const ulonglong2 a01 = *(const ulonglong2*)(&sA[kk * ASTR + (tr4 << 3)]);
            const ulonglong2 a23 = *(const ulonglong2*)(&sA[kk * ASTR + (tr4 << 3) + 4]);
            const ulonglong2 bp  = *(const ulonglong2*)(&sB[kk * GC + (tc4 << 2)]);
            acc[0][0] = ffma2(a01.x, bp.x, acc[0][0]);
            acc[0][1] = ffma2(a01.x, bp.y, acc[0][1]);
            acc[1][0] = ffma2(a01.y, bp.x, acc[1][0]);
            acc[1][1] = ffma2(a01.y, bp.y, acc[1][1]);
            acc[2][0] = ffma2(a23.x, bp.x, acc[2][0]);
            acc[2][1] = ffma2(a23.x, bp.y, acc[2][1]);
            acc[3][0] = ffma2(a23.y, bp.x, acc[3][0]);
            acc[3][1] = ffma2(a23.y, bp.y, acc[3][1]);
        }
    }
}

// ---------------- persistent LSTM kernel ------------------------------------
__global__ void __launch_bounds__(NTHREADS, 1)
lstm_persist(const float* __restrict__ input,   // [B,T]
             const float* __restrict__ Wx0,     // [2048]
             const float* __restrict__ Wh0,     // [512,2048]
             const float* __restrict__ b0,      // [2048]
             const float* __restrict__ Wx1,     // [512,2048]
             const float* __restrict__ Wh1,     // [512,2048]
             const float* __restrict__ b1)      // [2048]
{
    __shared__ float smem[4096];       // sA[16][132]=2112 | sB[16][64]=1024 ; Gs[64][64] overlays
    float* sA = smem;
    float* sB = smem + KB * ASTR;      // 2112
    float* Gs = smem;

    const int tid = threadIdx.x;
    const int bx  = blockIdx.x;        // 0..31  -> h-col block
    const int by  = blockIdx.y;        // 0..3   -> batch-row block
    const int r0  = by * TR;
    const int c0v = bx * TC;

    // microtile / staging index plan
    const int tc4   = tid & 15;        // col group (4 cols), also epilogue jj
    const int tr4   = tid >> 4;        // row group (4 rows), also epilogue rg
    const int a_row = tid >> 2;        // 0..63
    const int a_k   = (tid & 3) << 2;  // 0,4,8,12
    const int b_kk  = tid >> 4;        // 0..15
    const int b_q0  = (tid & 15) << 2; // 0..60
    const int aoff  = (r0 + a_row) * HH + a_k;
    const int boff  = b_kk * G4 + (b_q0 >> 4) * HH + c0v + (b_q0 & 15);

    // per-thread persistent state (4 h-elements per layer: rows 4*tr4+i, col jj)
    float c0r[4] = {0.f, 0.f, 0.f, 0.f};
    float c1r[4] = {0.f, 0.f, 0.f, 0.f};
    const int gc = c0v + tc4;
    float b0r[4], b1r[4], wxr[4];
    #pragma unroll
    for (int g = 0; g < 4; ++g) {
        b0r[g] = b0[g * HH + gc];
        b1r[g] = b1[g * HH + gc];
        wxr[g] = Wx0[g * HH + gc];
    }

    unsigned gen = *((volatile unsigned*)&g_gen);   // stable: no barrier can
    __syncthreads();                                 // complete before all read

    unsigned long long acc[4][2];

    for (int t = 0; t < TT; ++t) {
        // ================= layer 0 : G = h0_prev @ Wh0 =================
        const float* h0prev = t ? g_h0[1 - (t & 1)] : g_zeroh;
        float* h1buf = g_h0[t & 1];

        gemm_tile(h0prev, (const float*)0, Wh0, (const float*)0, HH / KB,
                  aoff, boff, sA, sB, tr4, tc4, a_row, a_k, b_kk, b_q0, acc);

        __syncthreads();
        #pragma unroll
        for (int i = 0; i < 4; ++i) {
            float x0, x1, x2, x3;
            upk2(acc[i][0], x0, x1);
            upk2(acc[i][1], x2, x3);
            *(float4*)(&Gs[(4 * tr4 + i) * GC + 4 * tc4]) = make_float4(x0, x1, x2, x3);
        }
        __syncthreads();

        #pragma unroll
        for (int i = 0; i < 4; ++i) {
            const int r  = 4 * tr4 + i;
            const int gr = r0 + r;
            const float xv = input[(size_t)gr * TT + t];
            float pre[4];
            #pragma unroll
            for (int g = 0; g < 4; ++g)
                pre[g] = Gs[r * GC + g * TC + tc4] + b0r[g] + xv * wxr[g];
            const float ig = sigmoidf_acc(pre[0]);
            const float fg = sigmoidf_acc(pre[1]);
            const float gg = tanhf(pre[2]);
            const float og = sigmoidf_acc(pre[3]);
            const float cn = fg * c0r[i] + ig * gg;
            c0r[i] = cn;
            h1buf[(size_t)gr * HH + gc] = og * tanhf(cn);
        }

        grid_bar(gen);   // publish h1[t] to all blocks (also orders H2[t-1])

        // ============ layer 1 : G = h1[t] @ Wx1 + h2[t-1] @ Wh1 ============
        const float* h2prev = t ? (g_H2 + (size_t)(t - 1) * BH) : g_zeroh;
        float* h2buf = g_H2 + (size_t)t * BH;

        gemm_tile(h1buf, h2prev, Wx1, Wh1, 2 * (HH / KB),
                  aoff, boff, sA, sB, tr4, tc4, a_row, a_k, b_kk, b_q0, acc);

        __syncthreads();
        #pragma unroll
        for (int i = 0; i < 4; ++i) {
            float x0, x1, x2, x3;
            upk2(acc[i][0], x0, x1);
            upk2(acc[i][1], x2, x3);
            *(float4*)(&Gs[(4 * tr4 + i) * GC + 4 * tc4]) = make_float4(x0, x1, x2, x3);
        }
        __syncthreads();

        #pragma unroll
        for (int i = 0; i < 4; ++i) {
            const int r  = 4 * tr4 + i;
            const int gr = r0 + r;
            float pre[4];
            #pragma unroll
            for (int g = 0; g < 4; ++g)
                pre[g] = Gs[r * GC + g * TC + tc4] + b1r[g];
            const float ig = sigmoidf_acc(pre[0]);
            const float fg = sigmoidf_acc(pre[1]);
            const float gg = tanhf(pre[2]);
            const float og = sigmoidf_acc(pre[3]);
            const float cn = fg * c1r[i] + ig * gg;
            c1r[i] = cn;
            h2buf[(size_t)gr * HH + gc] = og * tanhf(cn);
        }
        // no second barrier needed: layer0[t+1] touches only disjoint buffers;
        // the next step's grid_bar orders H2[t] before layer1[t+1] reads it.
    }
}

// ---------------- final projection: out[b,t] = h2[t,b,:] . Wf + bf ----------
__global__ void proj_kernel(const float* __restrict__ Wf,
                            const float* __restrict__ bf,
                            float* __restrict__ out)
{
    const int gw   = (int)(((size_t)blockIdx.x * blockDim.x + threadIdx.x) >> 5);
    const int lane = threadIdx.x & 31;
    if (gw >= BB * TT) return;
    const int b = gw & (BB - 1);
    const int t = gw >> 8;
    const float* h = g_H2 + ((size_t)t * BB + b) * HH;
    float s = 0.0f;
    #pragma unroll 4
    for (int k = lane; k < HH; k += 32) s += h[k] * Wf[k];
    #pragma unroll
    for (int o = 16; o > 0; o >>= 1) s += __shfl_xor_sync(0xffffffffu, s, o);
    if (lane == 0) out[(size_t)b * TT + t] = s + bf[0];
}

extern "C" void kernel_launch(void* const* d_in, const int* in_sizes, int n_in,
                              void* d_out, int out_size)
{
    (void)in_sizes; (void)n_in; (void)out_size;
    const float* input = (const float*)d_in[0];  // [256,1024]
    const float* Wx0   = (const float*)d_in[1];  // [1,2048]
    const float* Wh0   = (const float*)d_in[2];  // [512,2048]
    const float* b0    = (const float*)d_in[3];  // [2048]
    const float* Wx1   = (const float*)d_in[4];  // [512,2048]
    const float* Wh1   = (const float*)d_in[5];  // [512,2048]
    const float* b1    = (const float*)d_in[6];  // [2048]
    const float* Wf    = (const float*)d_in[7];  // [512]
    const float* bf    = (const float*)d_in[8];  // [1]
    float* out = (float*)d_out;                  // [256,1024]

    const dim3 grid(HH / TC, BB / TR);           // (32, 4) = 128 blocks
    lstm_persist<<<grid, NTHREADS>>>(input, Wx0, Wh0, b0, Wx1, Wh1, b1);

    proj_kernel<<<(BB * TT * 32 + 255) / 256, 256>>>(Wf, bf, out);
}